// round 2
// baseline (speedup 1.0000x reference)
#include <cuda_runtime.h>
#include <cmath>

#define BB 128
#define LL 512
#define HH 512
#define TT 24
#define TAG_START 22
#define TAG_STOP  23

// Scratch: X[b,l,t] = exp(emit[b,l,t]).  128*512*24 floats = 6.3 MB (L2-resident).
__device__ float g_X[BB * LL * TT];

// ---------------------------------------------------------------------------
// Kernel 1: emission GEMM + exp.  (unchanged — at the FFMA roofline)
// ---------------------------------------------------------------------------
__global__ __launch_bounds__(256) void emit_kernel(
    const float* __restrict__ feat,
    const float* __restrict__ Wm,
    const float* __restrict__ bias)
{
    __shared__ float Wsh[TT][HH];  // 48KB

    const int tid = threadIdx.x;

    const float4* Wv = reinterpret_cast<const float4*>(Wm);
    float4* Wshv = reinterpret_cast<float4*>(&Wsh[0][0]);
    #pragma unroll 4
    for (int i = tid; i < TT * HH / 4; i += 256) Wshv[i] = Wv[i];
    __syncthreads();

    const long row = (long)blockIdx.x * 256 + tid;
    const float4* fp = reinterpret_cast<const float4*>(feat + row * (long)HH);

    float acc[TT];
    #pragma unroll
    for (int t = 0; t < TT; ++t) acc[t] = 0.f;

    #pragma unroll 2
    for (int h4 = 0; h4 < HH / 4; ++h4) {
        const float4 f = fp[h4];
        const float4* wp = reinterpret_cast<const float4*>(&Wsh[0][0]) + h4;
        #pragma unroll
        for (int t = 0; t < TT; ++t) {
            const float4 wv = wp[t * (HH / 4)];
            acc[t] = fmaf(f.x, wv.x, acc[t]);
            acc[t] = fmaf(f.y, wv.y, acc[t]);
            acc[t] = fmaf(f.z, wv.z, acc[t]);
            acc[t] = fmaf(f.w, wv.w, acc[t]);
        }
    }

    float res[TT];
    #pragma unroll
    for (int t = 0; t < TT; ++t) res[t] = __expf(acc[t] + bias[t]);

    float4* op = reinterpret_cast<float4*>(g_X + row * TT);
    #pragma unroll
    for (int i = 0; i < TT / 4; ++i)
        op[i] = reinterpret_cast<const float4*>(res)[i];
}

// ---------------------------------------------------------------------------
// Kernel 2: linear-domain CRF scan. One warp per batch element.
// Unrolled-by-4 with a 4-deep explicit LDG prefetch ring so the emission
// loads pipeline across renamed registers (no per-iteration L2 stall).
// State updates are predicated on (t < len) — warp-uniform.
// ---------------------------------------------------------------------------
__global__ __launch_bounds__(256) void scan_kernel(
    const float* __restrict__ trans,
    const int*   __restrict__ lengths,
    float*       __restrict__ out)
{
    __shared__ float wsh[2][8][32];

    const int lane = threadIdx.x & 31;
    const int warp = threadIdx.x >> 5;
    const int b = blockIdx.x * 8 + warp;

    // E row for this lane; lanes >= 24 hold zeros.
    float E[TT];
    #pragma unroll
    for (int k = 0; k < TT; ++k)
        E[k] = (lane < TT) ? __expf(trans[lane * TT + k]) : 0.f;
    const float TE = (lane < TT) ? __expf(trans[TAG_STOP * TT + lane]) : 0.f;

    const int len = lengths[b];                 // 1..512, warp-uniform
    const float* Xb = g_X + (size_t)b * LL * TT;
    const bool lv = (lane < TT);

    float w = (lane == TAG_START) ? 1.f : 0.f;  // exp of initial alphas; 0 for lane>=24
    int   Mexp  = 0;
    float scale = 1.f;
    int   dpend = 0;

    // 4-deep prefetch ring
    float xq[4];
    #pragma unroll
    for (int u = 0; u < 4; ++u)
        xq[u] = lv ? Xb[u * TT + lane] : 0.f;

    for (int t0 = 0; t0 < LL; t0 += 4) {
        #pragma unroll
        for (int u = 0; u < 4; ++u) {
            const int t = t0 + u;
            const bool act = (t < len);   // warp-uniform

            wsh[u & 1][warp][lane] = w;

            // off-critical-path: pre-apply pending normalization to x
            const float pre = xq[u] * scale;

            // prefetch X for step t+4
            {
                const int tn = t + 4;
                if (lv && tn < LL) xq[u] = Xb[tn * TT + lane];
            }

            __syncwarp();

            // matvec: s = E_row . w  (6 broadcast float4 reads)
            const float4* wv = reinterpret_cast<const float4*>(wsh[u & 1][warp]);
            float a0 = 0.f, a1 = 0.f, a2 = 0.f, a3 = 0.f;
            #pragma unroll
            for (int q = 0; q < 6; ++q) {
                const float4 v = wv[q];
                a0 = fmaf(E[4 * q + 0], v.x, a0);
                a1 = fmaf(E[4 * q + 1], v.y, a1);
                a2 = fmaf(E[4 * q + 2], v.z, a2);
                a3 = fmaf(E[4 * q + 3], v.w, a3);
            }
            const float s = (a0 + a1) + (a2 + a3);
            const float wn = pre * s;     // zero for lanes >= 24 (xq==0)

            // exponent of max(wn): wn >= 0, raw bits ordered
            const unsigned mb = __reduce_max_sync(0xffffffffu, __float_as_uint(wn));
            const int e = (int)(mb >> 23);

            if (act) {
                w = wn;
                Mexp += dpend;            // consume previous pending exponent
                if (e == 0) { scale = 1.f; dpend = 0; }
                else {
                    dpend = e - 127;
                    scale = __uint_as_float((unsigned)(254 - e) << 23); // 2^-(e-127)
                }
            }
        }
        if (t0 + 4 >= len) break;
    }

    // fold in the last pending normalization: fv = ln(w) + Mexp*ln2
    w *= scale;
    Mexp += dpend;

    float term = w * TE;
    #pragma unroll
    for (int o = 16; o > 0; o >>= 1)
        term += __shfl_xor_sync(0xffffffffu, term, o);

    if (lane == 0)
        out[b] = __logf(term) + (float)Mexp * 0.69314718055994531f;
}

extern "C" void kernel_launch(void* const* d_in, const int* in_sizes, int n_in,
                              void* d_out, int out_size)
{
    const float* feat   = (const float*)d_in[0];  // [128,512,512]
    const float* Wm     = (const float*)d_in[1];  // [24,512]
    const float* bias   = (const float*)d_in[2];  // [24]
    const float* trans  = (const float*)d_in[3];  // [24,24]
    const int*   lens   = (const int*)d_in[4];    // [128]
    float* out = (float*)d_out;                   // [128]

    emit_kernel<<<256, 256>>>(feat, Wm, bias);
    scan_kernel<<<16, 256>>>(trans, lens, out);
}

// round 3
// speedup vs baseline: 1.1606x; 1.1606x over previous
#include <cuda_runtime.h>
#include <cmath>

#define BB 128
#define LL 512
#define HH 512
#define TT 24
#define TAG_START 22
#define TAG_STOP  23

// Scratch: X[b,l,t] = exp(emit[b,l,t]).  6.3 MB (L2-resident).
__device__ float g_X[BB * LL * TT];

// Packed fp32x2 FMA (FFMA2): d = a*b + c elementwise on 2xfp32 in 64-bit regs.
#define FMA2(d, a, b, c) \
    asm("fma.rn.f32x2 %0, %1, %2, %3;" : "=l"(d) : "l"(a), "l"(b), "l"(c))

// ---------------------------------------------------------------------------
// Kernel 1: emission GEMM + exp using packed f32x2 FMA (2x FFMA throughput).
// emit[row,t] = feat[row,:] . W[t,:] + bias[t];  X = exp(emit)
// 512 blocks x 128 threads: one thread per (b,l) row, W staged in smem.
// ---------------------------------------------------------------------------
__global__ __launch_bounds__(128) void emit_kernel(
    const float* __restrict__ feat,
    const float* __restrict__ Wm,
    const float* __restrict__ bias)
{
    __shared__ __align__(16) float Wsh[TT][HH];  // 48KB

    const int tid = threadIdx.x;

    // Cooperative load of W into shared (float4)
    const float4* Wv = reinterpret_cast<const float4*>(Wm);
    float4* Wshv = reinterpret_cast<float4*>(&Wsh[0][0]);
    #pragma unroll 4
    for (int i = tid; i < TT * HH / 4; i += 128) Wshv[i] = Wv[i];
    __syncthreads();

    const long row = (long)blockIdx.x * 128 + tid;   // 0..65535
    const ulonglong2* fp =
        reinterpret_cast<const ulonglong2*>(feat + row * (long)HH);

    unsigned long long acc2[TT];
    #pragma unroll
    for (int t = 0; t < TT; ++t) acc2[t] = 0ull;   // packed (0.f, 0.f)

    #pragma unroll 2
    for (int h4 = 0; h4 < HH / 4; ++h4) {
        const ulonglong2 f = fp[h4];               // 4 floats = 2 packed pairs
        const ulonglong2* wp =
            reinterpret_cast<const ulonglong2*>(&Wsh[0][0]) + h4;
        #pragma unroll
        for (int t = 0; t < TT; ++t) {
            const ulonglong2 wv = wp[t * (HH / 4)];  // broadcast LDS.128
            FMA2(acc2[t], f.x, wv.x, acc2[t]);
            FMA2(acc2[t], f.y, wv.y, acc2[t]);
        }
    }

    float res[TT];
    #pragma unroll
    for (int t = 0; t < TT; ++t) {
        const float lo = __uint_as_float((unsigned)(acc2[t] & 0xffffffffull));
        const float hi = __uint_as_float((unsigned)(acc2[t] >> 32));
        res[t] = __expf(lo + hi + bias[t]);
    }

    float4* op = reinterpret_cast<float4*>(g_X + row * TT);
    #pragma unroll
    for (int i = 0; i < TT / 4; ++i)
        op[i] = reinterpret_cast<const float4*>(res)[i];
}

// ---------------------------------------------------------------------------
// Kernel 2: linear-domain CRF scan, pure shuffle matvec (no smem, no barriers,
// branch-free state updates). One warp per block, one block per batch element.
// ---------------------------------------------------------------------------
__global__ __launch_bounds__(32) void scan_kernel(
    const float* __restrict__ trans,
    const int*   __restrict__ lengths,
    float*       __restrict__ out)
{
    const int lane = threadIdx.x;
    const int b = blockIdx.x;

    // E row for this lane; lanes >= 24 hold zeros.
    float E[TT];
    #pragma unroll
    for (int k = 0; k < TT; ++k)
        E[k] = (lane < TT) ? __expf(trans[lane * TT + k]) : 0.f;
    const float TE = (lane < TT) ? __expf(trans[TAG_STOP * TT + lane]) : 0.f;

    const int len = lengths[b];                 // 1..512, warp-uniform
    const float* Xb = g_X + (size_t)b * LL * TT;
    const bool lv = (lane < TT);

    float w = (lane == TAG_START) ? 1.f : 0.f;  // linear-domain state; 0 for lane>=24
    int   Mexp  = 0;
    float scale = 1.f;
    int   dpend = 0;

    // 8-deep prefetch ring
    float xq[8];
    #pragma unroll
    for (int u = 0; u < 8; ++u)
        xq[u] = lv ? Xb[u * TT + lane] : 0.f;

    for (int t0 = 0; t0 < LL; t0 += 8) {
        #pragma unroll
        for (int u = 0; u < 8; ++u) {
            const int t = t0 + u;
            const bool act = (t < len);         // warp-uniform

            // off-critical-path: apply pending normalization to emission
            const float pre = xq[u] * scale;

            // prefetch emission for step t+8 (predicated LDG)
            {
                const int tn = t + 8;
                if (lv && tn < LL) xq[u] = Xb[tn * TT + lane];
            }

            // matvec via register shuffles: s_j = sum_k E[j][k] * w_k
            float a0 = 0.f, a1 = 0.f, a2 = 0.f, a3 = 0.f;
            #pragma unroll
            for (int k = 0; k < TT; k += 4) {
                a0 = fmaf(E[k + 0], __shfl_sync(0xffffffffu, w, k + 0), a0);
                a1 = fmaf(E[k + 1], __shfl_sync(0xffffffffu, w, k + 1), a1);
                a2 = fmaf(E[k + 2], __shfl_sync(0xffffffffu, w, k + 2), a2);
                a3 = fmaf(E[k + 3], __shfl_sync(0xffffffffu, w, k + 3), a3);
            }
            const float s = (a0 + a1) + (a2 + a3);
            const float wn = pre * s;           // zero for lanes >= 24

            // exponent of max(wn): wn >= 0 so raw fp bits are order-preserving
            const unsigned mb =
                __reduce_max_sync(0xffffffffu, __float_as_uint(wn));
            const int e  = (int)(mb >> 23);
            const int en = (e == 0) ? 127 : e;  // degenerate guard
            const float nsc = __uint_as_float((unsigned)(254 - en) << 23);

            // branch-free (SEL) state updates, frozen once t >= len
            w     = act ? wn : w;
            Mexp  = act ? (Mexp + dpend) : Mexp;
            dpend = act ? (en - 127) : dpend;
            scale = act ? nsc : scale;
        }
        if (t0 + 8 >= len) break;
    }

    // fold in last pending normalization: fv = ln(w) + Mexp*ln2
    w *= scale;
    Mexp += dpend;

    float term = w * TE;
    #pragma unroll
    for (int o = 16; o > 0; o >>= 1)
        term += __shfl_xor_sync(0xffffffffu, term, o);

    if (lane == 0)
        out[b] = __logf(term) + (float)Mexp * 0.69314718055994531f;
}

extern "C" void kernel_launch(void* const* d_in, const int* in_sizes, int n_in,
                              void* d_out, int out_size)
{
    const float* feat   = (const float*)d_in[0];  // [128,512,512]
    const float* Wm     = (const float*)d_in[1];  // [24,512]
    const float* bias   = (const float*)d_in[2];  // [24]
    const float* trans  = (const float*)d_in[3];  // [24,24]
    const int*   lens   = (const int*)d_in[4];    // [128]
    float* out = (float*)d_out;                   // [128]

    emit_kernel<<<512, 128>>>(feat, Wm, bias);
    scan_kernel<<<128, 32>>>(trans, lens, out);
}

// round 5
// speedup vs baseline: 1.6703x; 1.4392x over previous
#include <cuda_runtime.h>
#include <cmath>

#define BB 128
#define LL 512
#define HH 512
#define TT 24
#define TAG_START 22
#define TAG_STOP  23

// Scratch: X[b,l,t] = exp(emit[b,l,t]).  6.3 MB (L2-resident).
__device__ float g_X[BB * LL * TT];

// m16n8k8 tf32 mma
#define MMA_TF32(c0,c1,c2,c3,a0,a1,a2,a3,b0,b1) \
  asm("mma.sync.aligned.m16n8k8.row.col.f32.tf32.tf32.f32 " \
      "{%0,%1,%2,%3},{%4,%5,%6,%7},{%8,%9},{%0,%1,%2,%3};" \
      : "+f"(c0),"+f"(c1),"+f"(c2),"+f"(c3) \
      : "r"(a0),"r"(a1),"r"(a2),"r"(a3),"r"(b0),"r"(b1))

__device__ __forceinline__ unsigned f2tf32(float v) {
    unsigned r;
    asm("cvt.rna.tf32.f32 %0, %1;" : "=r"(r) : "f"(v));
    return r;
}

// ---------------------------------------------------------------------------
// Kernel 1: emission GEMM + exp via tf32 tensor cores.  (unchanged from R4)
// C[65536,24] = F[65536,512] @ W^T[512,24];  X = exp(C + bias)
// ---------------------------------------------------------------------------
__global__ void __launch_bounds__(256, 4) emit_kernel(
    const float* __restrict__ feat,
    const float* __restrict__ Wm,
    const float* __restrict__ bias)
{
    __shared__ unsigned Wt[HH * TT];  // 48KB: tf32 bits, layout [k][n]

    const int tid = threadIdx.x;

    for (int i = tid; i < HH * TT; i += 256) {
        const int n = i >> 9;
        const int k = i & 511;
        Wt[k * TT + n] = f2tf32(Wm[i]);
    }
    __syncthreads();

    const int warp = tid >> 5;
    const int lane = tid & 31;
    const int g = lane >> 2;
    const int q = lane & 3;

    const long r0 = (long)blockIdx.x * 128 + warp * 16 + g;
    const float* pA  = feat + r0 * HH + q;
    const float* pA8 = pA + 8 * HH;

    float c0[3], c1[3], c2[3], c3[3];
    #pragma unroll
    for (int nt = 0; nt < 3; ++nt) { c0[nt]=0.f; c1[nt]=0.f; c2[nt]=0.f; c3[nt]=0.f; }

    #pragma unroll 4
    for (int k0 = 0; k0 < HH; k0 += 8) {
        const unsigned a0 = f2tf32(pA [k0]);
        const unsigned a1 = f2tf32(pA8[k0]);
        const unsigned a2 = f2tf32(pA [k0 + 4]);
        const unsigned a3 = f2tf32(pA8[k0 + 4]);

        const unsigned* wb0 = Wt + (k0 + q) * TT + g;
        const unsigned* wb1 = wb0 + 4 * TT;
        #pragma unroll
        for (int nt = 0; nt < 3; ++nt) {
            const unsigned b0 = wb0[nt * 8];
            const unsigned b1 = wb1[nt * 8];
            MMA_TF32(c0[nt], c1[nt], c2[nt], c3[nt], a0, a1, a2, a3, b0, b1);
        }
    }

    #pragma unroll
    for (int nt = 0; nt < 3; ++nt) {
        const int col = nt * 8 + 2 * q;
        const float bv0 = __ldg(bias + col);
        const float bv1 = __ldg(bias + col + 1);
        float2 lo = make_float2(__expf(c0[nt] + bv0), __expf(c1[nt] + bv1));
        float2 hi = make_float2(__expf(c2[nt] + bv0), __expf(c3[nt] + bv1));
        *reinterpret_cast<float2*>(g_X + r0 * TT + col)       = lo;
        *reinterpret_cast<float2*>(g_X + (r0 + 8) * TT + col) = hi;
    }
}

// ---------------------------------------------------------------------------
// Kernel 2: linear-domain CRF scan.  Round-3 bookkeeping verbatim (lag-1
// power-of-2 renorm, fp32 state); ONLY the exchange medium changed:
// bf16 through smem (1 STS.U16 + syncwarp + 3 broadcast LDS.128) instead of
// 24 serialized shuffles.  bf16 has fp32's exponent range, so exchanging the
// UNnormalized w is overflow-safe.
// ---------------------------------------------------------------------------
__global__ __launch_bounds__(32) void scan_kernel(
    const float* __restrict__ trans,
    const int*   __restrict__ lengths,
    float*       __restrict__ out)
{
    __shared__ __align__(16) unsigned short wbuf[2][32];

    const int lane = threadIdx.x;
    const int b = blockIdx.x;

    // E row for this lane; lanes >= 24 hold zeros.
    float E[TT];
    #pragma unroll
    for (int k = 0; k < TT; ++k)
        E[k] = (lane < TT) ? __expf(trans[lane * TT + k]) : 0.f;
    const float TE = (lane < TT) ? __expf(trans[TAG_STOP * TT + lane]) : 0.f;

    const int len = lengths[b];                 // 1..512, warp-uniform
    const float* Xb = g_X + (size_t)b * LL * TT;
    const bool lv = (lane < TT);

    float w = (lane == TAG_START) ? 1.f : 0.f;  // fp32 linear-domain state
    // bf16 bits of w for exchange (round-to-nearest; w >= 0, never NaN)
    unsigned short hs;
    { unsigned u = __float_as_uint(w);
      hs = (unsigned short)((u + 0x7fffu + ((u >> 16) & 1u)) >> 16); }

    int   Mexp  = 0;
    float scale = 1.f;
    int   dpend = 0;

    // 8-deep emission prefetch ring
    float xq[8];
    #pragma unroll
    for (int u = 0; u < 8; ++u)
        xq[u] = lv ? Xb[u * TT + lane] : 0.f;

    for (int t0 = 0; t0 < LL; t0 += 8) {
        #pragma unroll
        for (int u = 0; u < 8; ++u) {
            const int t = t0 + u;
            const bool act = (t < len);         // warp-uniform
            const int p = u & 1;

            wbuf[p][lane] = hs;

            // off-critical-path: apply pending normalization to emission
            const float pre = xq[u] * scale;

            // prefetch X for step t+8
            { const int tn = t + 8; if (lv && tn < LL) xq[u] = Xb[tn * TT + lane]; }

            __syncwarp();

            // read all 24 exchanged bf16 values (3 broadcast LDS.128)
            const uint4 v0 = *reinterpret_cast<const uint4*>(&wbuf[p][0]);
            const uint4 v1 = *reinterpret_cast<const uint4*>(&wbuf[p][8]);
            const uint4 v2 = *reinterpret_cast<const uint4*>(&wbuf[p][16]);
            unsigned pr[6] = { v0.x, v0.y, v0.z, v0.w, v1.x, v1.y };
            unsigned qr[6] = { v1.z, v1.w, v2.x, v2.y, v2.z, v2.w };

            // dot in fp32: s_j = sum_k E[j][k] * w_k  (bf16 -> f32 is a shift)
            float a0 = 0.f, a1 = 0.f, a2 = 0.f, a3 = 0.f;
            #pragma unroll
            for (int i = 0; i < 6; ++i) {
                const float wlo = __uint_as_float(pr[i] << 16);
                const float whi = __uint_as_float(pr[i] & 0xffff0000u);
                a0 = fmaf(E[2 * i + 0],  wlo, a0);
                a1 = fmaf(E[2 * i + 1],  whi, a1);
                const float ylo = __uint_as_float(qr[i] << 16);
                const float yhi = __uint_as_float(qr[i] & 0xffff0000u);
                a2 = fmaf(E[12 + 2 * i], ylo, a2);
                a3 = fmaf(E[13 + 2 * i], yhi, a3);
            }
            const float s = (a0 + a1) + (a2 + a3);
            const float wn = pre * s;           // zero for lanes >= 24 (pre==0)

            // bf16 bits of wn for the next exchange (off critical bookkeeping)
            unsigned short hn;
            { unsigned uu = __float_as_uint(wn);
              hn = (unsigned short)((uu + 0x7fffu + ((uu >> 16) & 1u)) >> 16); }

            // exponent of max(wn): wn >= 0 so raw bits are order-preserving
            const unsigned mb = __reduce_max_sync(0xffffffffu, __float_as_uint(wn));
            const int e  = (int)(mb >> 23);
            const int en = (e == 0) ? 127 : e;  // degenerate guard
            const float nsc = __uint_as_float((unsigned)(254 - en) << 23); // 2^-(en-127)

            // branch-free freeze (round-3 semantics)
            w     = act ? wn : w;
            hs    = act ? hn : hs;
            Mexp  = act ? (Mexp + dpend) : Mexp;
            dpend = act ? (en - 127) : dpend;
            scale = act ? nsc : scale;
        }
        if (t0 + 8 >= len) break;
    }

    // fold in last pending normalization: fv = ln(w) + Mexp*ln2
    w *= scale;
    Mexp += dpend;

    float term = w * TE;
    #pragma unroll
    for (int o = 16; o > 0; o >>= 1)
        term += __shfl_xor_sync(0xffffffffu, term, o);

    if (lane == 0)
        out[b] = __logf(term) + (float)Mexp * 0.69314718055994531f;
}

extern "C" void kernel_launch(void* const* d_in, const int* in_sizes, int n_in,
                              void* d_out, int out_size)
{
    const float* feat   = (const float*)d_in[0];  // [128,512,512]
    const float* Wm     = (const float*)d_in[1];  // [24,512]
    const float* bias   = (const float*)d_in[2];  // [24]
    const float* trans  = (const float*)d_in[3];  // [24,24]
    const int*   lens   = (const int*)d_in[4];    // [128]
    float* out = (float*)d_out;                   // [128]

    emit_kernel<<<512, 256>>>(feat, Wm, bias);
    scan_kernel<<<128, 32>>>(trans, lens, out);
}

// round 6
// speedup vs baseline: 1.7378x; 1.0404x over previous
#include <cuda_runtime.h>
#include <cmath>

#define BB 128
#define LL 512
#define HH 512
#define TT 24
#define TAG_START 22
#define TAG_STOP  23

// Scratch: X[b,l,t] = exp(emit[b,l,t]).  6.3 MB (L2-resident).
__device__ float g_X[BB * LL * TT];

// m16n8k8 tf32 mma
#define MMA_TF32(c0,c1,c2,c3,a0,a1,a2,a3,b0,b1) \
  asm("mma.sync.aligned.m16n8k8.row.col.f32.tf32.tf32.f32 " \
      "{%0,%1,%2,%3},{%4,%5,%6,%7},{%8,%9},{%0,%1,%2,%3};" \
      : "+f"(c0),"+f"(c1),"+f"(c2),"+f"(c3) \
      : "r"(a0),"r"(a1),"r"(a2),"r"(a3),"r"(b0),"r"(b1))

__device__ __forceinline__ unsigned f2tf32(float v) {
    unsigned r;
    asm("cvt.rna.tf32.f32 %0, %1;" : "=r"(r) : "f"(v));
    return r;
}

// ---------------------------------------------------------------------------
// Kernel 1: emission GEMM + exp via tf32 tensor cores, with an explicit
// 1-iteration A-register double buffer (keeps LDGs ~1 k-step ahead of use).
// C[65536,24] = F[65536,512] @ W^T[512,24];  X = exp(C + bias)
// ---------------------------------------------------------------------------
__global__ void __launch_bounds__(256, 4) emit_kernel(
    const float* __restrict__ feat,
    const float* __restrict__ Wm,
    const float* __restrict__ bias)
{
    __shared__ unsigned Wt[HH * TT];  // 48KB: tf32 bits, layout [k][n]

    const int tid = threadIdx.x;

    for (int i = tid; i < HH * TT; i += 256) {
        const int n = i >> 9;
        const int k = i & 511;
        Wt[k * TT + n] = f2tf32(Wm[i]);
    }
    __syncthreads();

    const int warp = tid >> 5;
    const int lane = tid & 31;
    const int g = lane >> 2;
    const int q = lane & 3;

    const long r0 = (long)blockIdx.x * 128 + warp * 16 + g;
    const float* pA  = feat + r0 * HH + q;
    const float* pA8 = pA + 8 * HH;

    float c0[3], c1[3], c2[3], c3[3];
    #pragma unroll
    for (int nt = 0; nt < 3; ++nt) { c0[nt]=0.f; c1[nt]=0.f; c2[nt]=0.f; c3[nt]=0.f; }

    // prefetch k0 = 0
    float f0 = pA[0], f1 = pA8[0], f2 = pA[4], f3 = pA8[4];

    #pragma unroll 4
    for (int k0 = 0; k0 < HH; k0 += 8) {
        // prefetch next iteration (clamped; reloading the last frag is harmless)
        const int kn = (k0 + 8 < HH) ? (k0 + 8) : (HH - 8);
        const float n0 = pA [kn];
        const float n1 = pA8[kn];
        const float n2 = pA [kn + 4];
        const float n3 = pA8[kn + 4];

        const unsigned a0 = f2tf32(f0);
        const unsigned a1 = f2tf32(f1);
        const unsigned a2 = f2tf32(f2);
        const unsigned a3 = f2tf32(f3);

        const unsigned* wb0 = Wt + (k0 + q) * TT + g;
        const unsigned* wb1 = wb0 + 4 * TT;
        #pragma unroll
        for (int nt = 0; nt < 3; ++nt) {
            const unsigned b0 = wb0[nt * 8];
            const unsigned b1 = wb1[nt * 8];
            MMA_TF32(c0[nt], c1[nt], c2[nt], c3[nt], a0, a1, a2, a3, b0, b1);
        }

        f0 = n0; f1 = n1; f2 = n2; f3 = n3;
    }

    #pragma unroll
    for (int nt = 0; nt < 3; ++nt) {
        const int col = nt * 8 + 2 * q;
        const float bv0 = __ldg(bias + col);
        const float bv1 = __ldg(bias + col + 1);
        float2 lo = make_float2(__expf(c0[nt] + bv0), __expf(c1[nt] + bv1));
        float2 hi = make_float2(__expf(c2[nt] + bv0), __expf(c3[nt] + bv1));
        *reinterpret_cast<float2*>(g_X + r0 * TT + col)       = lo;
        *reinterpret_cast<float2*>(g_X + (r0 + 8) * TT + col) = hi;
    }
}

// ---------------------------------------------------------------------------
// Kernel 2: linear-domain CRF scan, minimal per-step critical path:
//   STS.32(w) -> syncwarp -> 6x broadcast LDS.128 -> 24 FFMA -> FMUL
// Renormalization (REDUX + power-of-2 rescale) amortized to every 4 steps and
// applied UNCONDITIONALLY: w *= 2^-d, Mexp += d preserves w*2^Mexp exactly,
// so it is a semantic no-op on both active and frozen chains (range control
// only; growth <= ~2^16/step -> 4 steps fit in fp32 with huge margin).
// Prefetch is branch-free (clamped index + SEL), no BSSY/BSYNC in the body.
// ---------------------------------------------------------------------------
__global__ __launch_bounds__(32) void scan_kernel(
    const float* __restrict__ trans,
    const int*   __restrict__ lengths,
    float*       __restrict__ out)
{
    __shared__ __align__(16) float wbuf[2][32];

    const int lane = threadIdx.x;
    const int b = blockIdx.x;

    // E row for this lane; lanes >= 24 hold zeros.
    float E[TT];
    #pragma unroll
    for (int k = 0; k < TT; ++k)
        E[k] = (lane < TT) ? __expf(trans[lane * TT + k]) : 0.f;
    const float TE = (lane < TT) ? __expf(trans[TAG_STOP * TT + lane]) : 0.f;

    const int len = lengths[b];                 // 1..512, warp-uniform
    const int lanec = (lane < TT) ? lane : (TT - 1);
    const float* Xb = g_X + (size_t)b * LL * TT;
    const bool lv = (lane < TT);

    float w = (lane == TAG_START) ? 1.f : 0.f;  // fp32 linear-domain state
    int   Mexp = 0;

    // 8-deep emission prefetch ring (branch-free fill)
    float xq[8];
    #pragma unroll
    for (int u = 0; u < 8; ++u)
        xq[u] = lv ? Xb[u * TT + lane] : 0.f;

    for (int t0 = 0; t0 < LL; t0 += 8) {
        #pragma unroll
        for (int u = 0; u < 8; ++u) {
            const int t = t0 + u;
            const bool act = (t < len);         // warp-uniform
            const int p = u & 1;

            wbuf[p][lane] = w;                  // STS.32 — starts the exchange

            // branch-free prefetch of X for step t+8 (clamped, always issued)
            const int tn = (t + 8 < LL) ? (t + 8) : (LL - 1);
            const float xl = Xb[tn * TT + lanec];

            __syncwarp();

            // s_j = sum_k E[j][k] * w_k  (6 broadcast LDS.128)
            const float4* wv = reinterpret_cast<const float4*>(&wbuf[p][0]);
            float a0 = 0.f, a1 = 0.f, a2 = 0.f, a3 = 0.f;
            #pragma unroll
            for (int qq = 0; qq < 6; ++qq) {
                const float4 v = wv[qq];
                a0 = fmaf(E[4 * qq + 0], v.x, a0);
                a1 = fmaf(E[4 * qq + 1], v.y, a1);
                a2 = fmaf(E[4 * qq + 2], v.z, a2);
                a3 = fmaf(E[4 * qq + 3], v.w, a3);
            }
            const float s = (a0 + a1) + (a2 + a3);
            const float wn = xq[u] * s;         // zero for lanes >= 24

            w = act ? wn : w;                   // freeze (SEL)
            xq[u] = lv ? xl : 0.f;              // rotate prefetch (SEL)

            // amortized unconditional renorm every 4 steps
            if ((u & 3) == 3) {
                const unsigned mb =
                    __reduce_max_sync(0xffffffffu, __float_as_uint(w));
                const int e  = (int)(mb >> 23);
                const int en = (e == 0) ? 127 : e;
                const float nsc =
                    __uint_as_float((unsigned)(254 - en) << 23); // 2^-(en-127)
                w *= nsc;
                Mexp += (en - 127);   // w * 2^Mexp invariant — safe when frozen
            }
        }
        if (t0 + 8 >= len) break;
    }

    // alpha = log( sum_k w_k * TE_k ) + Mexp*ln2
    float term = w * TE;
    #pragma unroll
    for (int o = 16; o > 0; o >>= 1)
        term += __shfl_xor_sync(0xffffffffu, term, o);

    if (lane == 0)
        out[b] = __logf(term) + (float)Mexp * 0.69314718055994531f;
}

extern "C" void kernel_launch(void* const* d_in, const int* in_sizes, int n_in,
                              void* d_out, int out_size)
{
    const float* feat   = (const float*)d_in[0];  // [128,512,512]
    const float* Wm     = (const float*)d_in[1];  // [24,512]
    const float* bias   = (const float*)d_in[2];  // [24]
    const float* trans  = (const float*)d_in[3];  // [24,24]
    const int*   lens   = (const int*)d_in[4];    // [128]
    float* out = (float*)d_out;                   // [128]

    emit_kernel<<<512, 256>>>(feat, Wm, bias);
    scan_kernel<<<128, 32>>>(trans, lens, out);
}